// round 14
// baseline (speedup 1.0000x reference)
#include <cuda_runtime.h>
#include <cuda_fp16.h>
#include <math.h>
#include <stdint.h>

#define B_    8192
#define D_    1024
#define H_    4096
#define E_    8
#define NSLOT (B_ * 2)
#define RMAX  17408   // 16384 + 8*128 tile padding

// ---------------- scratch (device globals: allocation-free) ----------------
__device__ __align__(128) __half g_h[(size_t)RMAX * H_];     // gelu(fc1), fp16
__device__ __align__(128) __half g_o[(size_t)RMAX * D_];     // fc2 out, fp16
__device__ __align__(128) __half g_xh[(size_t)B_ * D_];      // x in fp16
__device__ __align__(128) __half g_w1h[(size_t)E_ * H_ * D_];
__device__ __align__(128) __half g_w2h[(size_t)E_ * D_ * H_];
__device__ int   g_tok[RMAX];
__device__ int   g_pos[NSLOT];
__device__ int   g_eidx[NSLOT];
__device__ float g_gval[NSLOT];
__device__ int   g_cnt[E_];
__device__ int   g_cur[E_];
__device__ int   g_off[E_ + 1];
__device__ float g_imp[E_];

// ---------------- helpers ----------------------------------------------------
__device__ __forceinline__ uint32_t smem_u32(const void* p) {
    uint32_t a;
    asm("{ .reg .u64 t; cvta.to.shared.u64 t, %1; cvt.u32.u64 %0, t; }" : "=r"(a) : "l"(p));
    return a;
}
__device__ __forceinline__ void ldmx4(uint32_t& r0, uint32_t& r1, uint32_t& r2, uint32_t& r3,
                                      uint32_t addr) {
    asm volatile("ldmatrix.sync.aligned.m8n8.x4.shared.b16 {%0,%1,%2,%3}, [%4];"
                 : "=r"(r0), "=r"(r1), "=r"(r2), "=r"(r3) : "r"(addr));
}
__device__ __forceinline__ void mma16816(float* c, const uint32_t* a, uint32_t b0, uint32_t b1) {
    asm volatile("mma.sync.aligned.m16n8k16.row.col.f32.f16.f16.f32 "
                 "{%0,%1,%2,%3}, {%4,%5,%6,%7}, {%8,%9}, {%0,%1,%2,%3};"
                 : "+f"(c[0]), "+f"(c[1]), "+f"(c[2]), "+f"(c[3])
                 : "r"(a[0]), "r"(a[1]), "r"(a[2]), "r"(a[3]), "r"(b0), "r"(b1));
}
__device__ __forceinline__ void cp16(uint32_t dst, const void* src) {
    asm volatile("cp.async.cg.shared.global [%0], [%1], 16;" :: "r"(dst), "l"(src));
}
__device__ __forceinline__ void cp_commit() {
    asm volatile("cp.async.commit_group;" ::: "memory");
}
__device__ __forceinline__ void cp_wait0() {
    asm volatile("cp.async.wait_group 0;" ::: "memory");
}

// ---------------- 0) fp32 -> fp16 conversion ---------------------------------
__global__ void cvt_f2h(const float4* __restrict__ src, uint4* __restrict__ dst, int n8)
{
    int i = blockIdx.x * blockDim.x + threadIdx.x;
    if (i < n8) {
        float4 a = __ldg(&src[2 * i]);
        float4 b = __ldg(&src[2 * i + 1]);
        __half2 h0 = __floats2half2_rn(a.x, a.y);
        __half2 h1 = __floats2half2_rn(a.z, a.w);
        __half2 h2 = __floats2half2_rn(b.x, b.y);
        __half2 h3 = __floats2half2_rn(b.z, b.w);
        dst[i] = make_uint4(*(uint32_t*)&h0, *(uint32_t*)&h1,
                            *(uint32_t*)&h2, *(uint32_t*)&h3);
    }
}

// ---------------- 1) gating (float4 vectorized) -------------------------------
__global__ void gating_kernel(const float* __restrict__ x,
                              const float* __restrict__ wg)
{
    __shared__ float ws[E_ * D_];
    for (int i = threadIdx.x; i < E_ * D_ / 4; i += blockDim.x)
        ((float4*)ws)[i] = ((const float4*)wg)[i];
    __syncthreads();

    const int warp = threadIdx.x >> 5, lane = threadIdx.x & 31;
    const int b = blockIdx.x * 8 + warp;
    const float4* xr = (const float4*)(x + (size_t)b * D_);

    float acc[E_];
#pragma unroll
    for (int e = 0; e < E_; e++) acc[e] = 0.f;
    for (int d4 = lane; d4 < D_ / 4; d4 += 32) {
        float4 xv = __ldg(&xr[d4]);
#pragma unroll
        for (int e = 0; e < E_; e++) {
            float4 wv = ((const float4*)(ws + e * D_))[d4];
            acc[e] = fmaf(xv.x, wv.x, acc[e]);
            acc[e] = fmaf(xv.y, wv.y, acc[e]);
            acc[e] = fmaf(xv.z, wv.z, acc[e]);
            acc[e] = fmaf(xv.w, wv.w, acc[e]);
        }
    }
#pragma unroll
    for (int e = 0; e < E_; e++) {
#pragma unroll
        for (int o = 16; o; o >>= 1) acc[e] += __shfl_down_sync(0xffffffffu, acc[e], o);
    }
    if (lane == 0) {
        int i0 = 0; float v0 = acc[0];
#pragma unroll
        for (int e = 1; e < E_; e++) if (acc[e] > v0) { v0 = acc[e]; i0 = e; }
        int i1 = -1; float v1 = -INFINITY;
#pragma unroll
        for (int e = 0; e < E_; e++) if (e != i0 && acc[e] > v1) { v1 = acc[e]; i1 = e; }
        float t  = expf(v1 - v0);
        float gA = 1.f / (1.f + t);
        float gB = t / (1.f + t);
        g_eidx[b * 2 + 0] = i0;  g_eidx[b * 2 + 1] = i1;
        g_gval[b * 2 + 0] = gA;  g_gval[b * 2 + 1] = gB;
    }
}

// ---------------- 2) per-expert stats ----------------------------------------
__global__ void expert_stats_kernel()
{
    const int e = blockIdx.x;
    const int tid = threadIdx.x;
    float imp = 0.f; int cnt = 0;
    for (int i = tid; i < NSLOT; i += 256)
        if (g_eidx[i] == e) { imp += g_gval[i]; cnt++; }
    __shared__ float simp[256];
    __shared__ int   scnt[256];
    simp[tid] = imp; scnt[tid] = cnt;
    __syncthreads();
    for (int s = 128; s; s >>= 1) {
        if (tid < s) { simp[tid] += simp[tid + s]; scnt[tid] += scnt[tid + s]; }
        __syncthreads();
    }
    if (tid == 0) { g_imp[e] = simp[0]; g_cnt[e] = scnt[0]; }
}

// ---------------- 3) scan + loss ----------------------------------------------
__global__ void scan_loss_kernel(float* __restrict__ out)
{
    if (threadIdx.x == 0 && blockIdx.x == 0) {
        int off = 0;
        for (int e = 0; e < E_; e++) {
            g_off[e] = off; g_cur[e] = off;
            off += ((g_cnt[e] + 127) >> 7) << 7;
        }
        g_off[E_] = off;
        float mi = 0.f, ml = 0.f;
        for (int e = 0; e < E_; e++) { mi += g_imp[e]; ml += (float)g_cnt[e]; }
        mi *= (1.f / E_); ml *= (1.f / E_);
        float vi = 0.f, vl = 0.f;
        for (int e = 0; e < E_; e++) {
            float di = g_imp[e] - mi;        vi += di * di;
            float dl = (float)g_cnt[e] - ml; vl += dl * dl;
        }
        vi *= (1.f / (E_ - 1)); vl *= (1.f / (E_ - 1));
        out[(size_t)B_ * D_] = (vi / (mi * mi + 1e-10f) + vl / (ml * ml + 1e-10f)) * 0.01f;
    }
}

// ---------------- 4) scatter ---------------------------------------------------
__global__ void scatter_kernel()
{
    int i = blockIdx.x * blockDim.x + threadIdx.x;
    if (i < NSLOT) {
        int e = g_eidx[i];
        int pos = atomicAdd(&g_cur[e], 1);
        g_tok[pos] = i >> 1;
        g_pos[i] = pos;
    }
}

// ---------------- 5/6) grouped GEMM, 128x128, 2-stage, ks-pipelined LDSM ------
#define LDS_ 72
#define MAT_HALVES (128 * LDS_)               // 9216 per matrix per stage
#define STG_BYTES  (2 * MAT_HALVES * 2)       // 36864
#define SMEM_TOT   (2 * STG_BYTES)            // 73728  (>= 128*272 staging)

template<int NFULL, int KDIM, bool PH1, bool NMAJOR>
__global__ __launch_bounds__(256, 2)
void gemm_mma(const __half* __restrict__ A, const __half* __restrict__ W,
              const float* __restrict__ bias)
{
    extern __shared__ __half smem[];

    const int row0 = (NMAJOR ? blockIdx.y : blockIdx.x) * 128;
    if (row0 >= g_off[E_]) return;

    int e = 0;
#pragma unroll
    for (int i = 0; i < E_; i++) if (row0 >= g_off[i + 1]) e = i + 1;
    const int rowEnd = g_off[e] + g_cnt[e];

    const int tid = threadIdx.x;
    const int w = tid >> 5, lane = tid & 31;
    const int wm = w & 3, wn = w >> 2;
    const int n0 = (NMAJOR ? blockIdx.x : blockIdx.y) * 128;
    const __half* We = W + (size_t)e * NFULL * KDIM;

    const uint32_t sb = smem_u32(smem);

    const __half* pB[4];
    const __half* pA[4];
    uint32_t offA[4], offB[4];
#pragma unroll
    for (int i = 0; i < 4; i++) {
        int idx = tid + i * 256;
        int row = idx >> 3, q = idx & 7;
        offA[i] = (row * LDS_ + q * 8) * 2;
        offB[i] = (MAT_HALVES + row * LDS_ + q * 8) * 2;
        pB[i] = We + (size_t)(n0 + row) * KDIM + q * 8;
        if (PH1) {
            int tok = g_tok[row0 + row];
            pA[i] = A + (size_t)tok * KDIM + q * 8;
        } else {
            pA[i] = A + (size_t)(row0 + row) * KDIM + q * 8;
        }
    }

    float acc[2][8][4];
#pragma unroll
    for (int a = 0; a < 2; a++)
#pragma unroll
        for (int b = 0; b < 8; b++)
#pragma unroll
            for (int c = 0; c < 4; c++) acc[a][b][c] = 0.f;

    const int NC = KDIM / 64;

    // fragment-address helpers (per ks: kk = ks*16)
    const uint32_t aoffBase = ((wm * 32 + (lane & 15)) * LDS_ + ((lane >> 4) << 3)) * 2;
    const uint32_t boffBase = ((wn * 64 + ((lane >> 4) << 3) + (lane & 7)) * LDS_
                               + (((lane >> 3) & 1) << 3)) * 2;

    // prologue: stage 0
    {
#pragma unroll
        for (int i = 0; i < 4; i++) {
            cp16(sb + offA[i], pA[i]);
            cp16(sb + offB[i], pB[i]);
        }
        cp_commit();
    }

    for (int c = 0; c < NC; c++) {
        cp_wait0();
        __syncthreads();

        if (c + 1 < NC) {
            const int k1 = (c + 1) * 64;
            uint32_t base = sb + ((c + 1) & 1) * STG_BYTES;
#pragma unroll
            for (int i = 0; i < 4; i++) {
                cp16(base + offA[i], pA[i] + k1);
                cp16(base + offB[i], pB[i] + k1);
            }
            cp_commit();
        }

        const uint32_t sbA = sb + (c & 1) * STG_BYTES;
        const uint32_t sbB = sbA + MAT_HALVES * 2;

        // register double-buffer over ks: load frags(ks+1) before mma(ks)
        uint32_t aF[2][2][4];   // [buf][mf][reg]
        uint32_t bF[2][4][4];   // [buf][j2][reg]

        // load ks=0 into buf 0
#pragma unroll
        for (int mf = 0; mf < 2; mf++)
            ldmx4(aF[0][mf][0], aF[0][mf][1], aF[0][mf][2], aF[0][mf][3],
                  sbA + aoffBase + (mf * 16 * LDS_) * 2);
#pragma unroll
        for (int j2 = 0; j2 < 4; j2++)
            ldmx4(bF[0][j2][0], bF[0][j2][1], bF[0][j2][2], bF[0][j2][3],
                  sbB + boffBase + (j2 * 16 * LDS_) * 2);

#pragma unroll
        for (int ks = 0; ks < 4; ks++) {
            const int cur = ks & 1, nxt = cur ^ 1;
            if (ks < 3) {
                const uint32_t kk2 = (ks + 1) * 16 * 2;
#pragma unroll
                for (int mf = 0; mf < 2; mf++)
                    ldmx4(aF[nxt][mf][0], aF[nxt][mf][1], aF[nxt][mf][2], aF[nxt][mf][3],
                          sbA + aoffBase + kk2 + (mf * 16 * LDS_) * 2);
#pragma unroll
                for (int j2 = 0; j2 < 4; j2++)
                    ldmx4(bF[nxt][j2][0], bF[nxt][j2][1], bF[nxt][j2][2], bF[nxt][j2][3],
                          sbB + boffBase + kk2 + (j2 * 16 * LDS_) * 2);
            }
#pragma unroll
            for (int j2 = 0; j2 < 4; j2++) {
#pragma unroll
                for (int mf = 0; mf < 2; mf++) {
#pragma unroll
                    for (int nf = 0; nf < 2; nf++)
                        mma16816(acc[mf][j2 * 2 + nf], aF[cur][mf],
                                 bF[cur][j2][2 * nf], bF[cur][j2][2 * nf + 1]);
                }
            }
        }
    }
    cp_wait0();
    __syncthreads();   // all ldsm done; smem free for staging

    // ---- epilogue: stage tile in SMEM, then coalesced 16B stores ----
    const int g = lane >> 2, cpair = lane & 3;
#pragma unroll
    for (int mf = 0; mf < 2; mf++) {
#pragma unroll
        for (int nf = 0; nf < 8; nf++) {
            int col = wn * 64 + nf * 8 + 2 * cpair;
            float b0 = __ldg(&bias[(size_t)e * NFULL + n0 + col]);
            float b1 = __ldg(&bias[(size_t)e * NFULL + n0 + col + 1]);
            float* cc = acc[mf][nf];
#pragma unroll
            for (int half = 0; half < 2; half++) {
                int lrow = wm * 32 + mf * 16 + half * 8 + g;
                float v0 = cc[half * 2 + 0] + b0;
                float v1 = cc[half * 2 + 1] + b1;
                if (PH1) {
                    v0 = 0.5f * v0 * (1.0f + erff(v0 * 0.7071067811865476f));
                    v1 = 0.5f * v1 * (1.0f + erff(v1 * 0.7071067811865476f));
                }
                __half2 hw = __floats2half2_rn(v0, v1);
                *(uint32_t*)((char*)smem + (lrow * 136 + col) * 2) = *(uint32_t*)&hw;
            }
        }
    }
    __syncthreads();

    __half* dstBase = PH1 ? g_h : g_o;
    for (int i = tid; i < 128 * 16; i += 256) {
        int row = i >> 4, seg = i & 15;
        int r = row0 + row;
        if (r < rowEnd) {
            uint4 v = *(uint4*)((char*)smem + row * 272 + seg * 16);
            *(uint4*)&dstBase[(size_t)r * NFULL + n0 + seg * 8] = v;
        }
    }
}

// ---------------- 7) dual softmax + combine + log -----------------------------
__global__ void combine_kernel(float* __restrict__ out)
{
    __shared__ float s0[D_], s1[D_];
    __shared__ float r0[8], r1[8];

    const int b = blockIdx.x;
    const int tid = threadIdx.x;
    const int lane = tid & 31, warp = tid >> 5;

    const int   p0 = g_pos[b * 2 + 0], p1 = g_pos[b * 2 + 1];
    const float gg0 = g_gval[b * 2 + 0], gg1 = g_gval[b * 2 + 1];
    const __half* q0 = g_o + (size_t)p0 * D_;
    const __half* q1 = g_o + (size_t)p1 * D_;

    float m0 = -INFINITY, m1 = -INFINITY;
    for (int d = tid; d < D_; d += 256) {
        float v0 = __half2float(q0[d]), v1 = __half2float(q1[d]);
        s0[d] = v0; s1[d] = v1;
        m0 = fmaxf(m0, v0); m1 = fmaxf(m1, v1);
    }
#pragma unroll
    for (int o = 16; o; o >>= 1) {
        m0 = fmaxf(m0, __shfl_down_sync(0xffffffffu, m0, o));
        m1 = fmaxf(m1, __shfl_down_sync(0xffffffffu, m1, o));
    }
    if (lane == 0) { r0[warp] = m0; r1[warp] = m1; }
    __syncthreads();
    if (tid == 0) {
        float a = r0[0], c = r1[0];
        for (int i = 1; i < 8; i++) { a = fmaxf(a, r0[i]); c = fmaxf(c, r1[i]); }
        r0[0] = a; r1[0] = c;
    }
    __syncthreads();
    m0 = r0[0]; m1 = r1[0];

    float e0 = 0.f, e1 = 0.f;
    for (int d = tid; d < D_; d += 256) {
        e0 += expf(s0[d] - m0);
        e1 += expf(s1[d] - m1);
    }
#pragma unroll
    for (int o = 16; o; o >>= 1) {
        e0 += __shfl_down_sync(0xffffffffu, e0, o);
        e1 += __shfl_down_sync(0xffffffffu, e1, o);
    }
    __syncthreads();
    if (lane == 0) { r0[warp] = e0; r1[warp] = e1; }
    __syncthreads();
    if (tid == 0) {
        float a = 0.f, c = 0.f;
        for (int i = 0; i < 8; i++) { a += r0[i]; c += r1[i]; }
        r0[0] = a; r1[0] = c;
    }
    __syncthreads();
    const float c0 = gg0 / r0[0];
    const float c1 = gg1 / r1[0];

    for (int d = tid; d < D_; d += 256) {
        float c = c0 * expf(s0[d] - m0) + c1 * expf(s1[d] - m1);
        if (c == 0.f) c = 2.2204460492503131e-16f;
        out[(size_t)b * D_ + d] = logf(c);
    }
}

// ---------------- launch --------------------------------------------------------
extern "C" void kernel_launch(void* const* d_in, const int* in_sizes, int n_in,
                              void* d_out, int out_size)
{
    const float* x    = (const float*)d_in[0];
    const float* wg   = (const float*)d_in[1];
    const float* fc1w = (const float*)d_in[2];
    const float* fc1b = (const float*)d_in[3];
    const float* fc2w = (const float*)d_in[4];
    const float* fc2b = (const float*)d_in[5];
    float* out = (float*)d_out;

    __half* xh;  cudaGetSymbolAddress((void**)&xh,  g_xh);
    __half* w1h; cudaGetSymbolAddress((void**)&w1h, g_w1h);
    __half* w2h; cudaGetSymbolAddress((void**)&w2h, g_w2h);
    __half* hh;  cudaGetSymbolAddress((void**)&hh,  g_h);

    static cudaStream_t s1 = nullptr, s2 = nullptr;
    static cudaEvent_t ev0 = nullptr, ev1 = nullptr, ev2 = nullptr;
    if (!s1) {
        cudaStreamCreateWithFlags(&s1, cudaStreamNonBlocking);
        cudaStreamCreateWithFlags(&s2, cudaStreamNonBlocking);
        cudaEventCreateWithFlags(&ev0, cudaEventDisableTiming);
        cudaEventCreateWithFlags(&ev1, cudaEventDisableTiming);
        cudaEventCreateWithFlags(&ev2, cudaEventDisableTiming);
        cudaFuncSetAttribute(gemm_mma<H_, D_, true, false>,
                             cudaFuncAttributeMaxDynamicSharedMemorySize, SMEM_TOT);
        cudaFuncSetAttribute(gemm_mma<D_, H_, false, true>,
                             cudaFuncAttributeMaxDynamicSharedMemorySize, SMEM_TOT);
    }

    const int nW = E_ * H_ * D_ / 8;     // 4194304
    const int nX = B_ * D_ / 8;          // 1048576

    cudaEventRecord(ev0, 0);
    cudaStreamWaitEvent(s1, ev0, 0);
    cudaStreamWaitEvent(s2, ev0, 0);

    cvt_f2h<<<(nX + 255) / 256, 256, 0, s1>>>((const float4*)x,    (uint4*)xh,  nX);
    cvt_f2h<<<(nW + 255) / 256, 256, 0, s1>>>((const float4*)fc1w, (uint4*)w1h, nW);
    cudaEventRecord(ev1, s1);

    cvt_f2h<<<(nW + 255) / 256, 256, 0, s2>>>((const float4*)fc2w, (uint4*)w2h, nW);
    cudaEventRecord(ev2, s2);

    gating_kernel<<<B_ / 8, 256>>>(x, wg);
    expert_stats_kernel<<<E_, 256>>>();
    scan_loss_kernel<<<1, 32>>>(out);
    scatter_kernel<<<(NSLOT + 255) / 256, 256>>>();

    cudaStreamWaitEvent(0, ev1, 0);
    gemm_mma<H_, D_, true, false><<<dim3(RMAX / 128, H_ / 128), 256, SMEM_TOT>>>(xh, w1h, fc1b);

    cudaStreamWaitEvent(0, ev2, 0);
    gemm_mma<D_, H_, false, true><<<dim3(D_ / 128, RMAX / 128), 256, SMEM_TOT>>>(hh, w2h, fc2b);

    combine_kernel<<<B_, 256>>>(out);
}

// round 15
// speedup vs baseline: 1.0001x; 1.0001x over previous
#include <cuda_runtime.h>
#include <cuda_fp16.h>
#include <math.h>
#include <stdint.h>

#define B_    8192
#define D_    1024
#define H_    4096
#define E_    8
#define NSLOT (B_ * 2)
#define RMAX  17408   // 16384 + 8*128 tile padding

// ---------------- scratch (device globals: allocation-free) ----------------
__device__ __align__(128) __half g_h[(size_t)RMAX * H_];     // gelu(fc1), fp16
__device__ __align__(128) __half g_o[(size_t)RMAX * D_];     // fc2 out, fp16
__device__ __align__(128) __half g_xh[(size_t)B_ * D_];      // x in fp16
__device__ __align__(128) __half g_w1h[(size_t)E_ * H_ * D_];
__device__ __align__(128) __half g_w2h[(size_t)E_ * D_ * H_];
__device__ int   g_tok[RMAX];
__device__ int   g_pos[NSLOT];
__device__ int   g_eidx[NSLOT];
__device__ float g_gval[NSLOT];
__device__ int   g_cnt[E_];
__device__ int   g_cur[E_];
__device__ int   g_off[E_ + 1];

// ---------------- helpers ----------------------------------------------------
__device__ __forceinline__ uint32_t smem_u32(const void* p) {
    uint32_t a;
    asm("{ .reg .u64 t; cvta.to.shared.u64 t, %1; cvt.u32.u64 %0, t; }" : "=r"(a) : "l"(p));
    return a;
}
__device__ __forceinline__ void ldmx4(uint32_t& r0, uint32_t& r1, uint32_t& r2, uint32_t& r3,
                                      uint32_t addr) {
    asm volatile("ldmatrix.sync.aligned.m8n8.x4.shared.b16 {%0,%1,%2,%3}, [%4];"
                 : "=r"(r0), "=r"(r1), "=r"(r2), "=r"(r3) : "r"(addr));
}
__device__ __forceinline__ void mma16816(float* c, const uint32_t* a, uint32_t b0, uint32_t b1) {
    asm volatile("mma.sync.aligned.m16n8k16.row.col.f32.f16.f16.f32 "
                 "{%0,%1,%2,%3}, {%4,%5,%6,%7}, {%8,%9}, {%0,%1,%2,%3};"
                 : "+f"(c[0]), "+f"(c[1]), "+f"(c[2]), "+f"(c[3])
                 : "r"(a[0]), "r"(a[1]), "r"(a[2]), "r"(a[3]), "r"(b0), "r"(b1));
}
__device__ __forceinline__ void cp16(uint32_t dst, const void* src) {
    asm volatile("cp.async.cg.shared.global [%0], [%1], 16;" :: "r"(dst), "l"(src));
}
__device__ __forceinline__ void cp_commit() {
    asm volatile("cp.async.commit_group;" ::: "memory");
}
__device__ __forceinline__ void cp_wait0() {
    asm volatile("cp.async.wait_group 0;" ::: "memory");
}

// ---------------- 0) fp32 -> fp16 conversion ---------------------------------
__global__ void cvt_f2h(const float4* __restrict__ src, uint4* __restrict__ dst, int n8)
{
    int i = blockIdx.x * blockDim.x + threadIdx.x;
    if (i < n8) {
        float4 a = __ldg(&src[2 * i]);
        float4 b = __ldg(&src[2 * i + 1]);
        __half2 h0 = __floats2half2_rn(a.x, a.y);
        __half2 h1 = __floats2half2_rn(a.z, a.w);
        __half2 h2 = __floats2half2_rn(b.x, b.y);
        __half2 h3 = __floats2half2_rn(b.z, b.w);
        dst[i] = make_uint4(*(uint32_t*)&h0, *(uint32_t*)&h1,
                            *(uint32_t*)&h2, *(uint32_t*)&h3);
    }
}

// ---------------- 1) gating (float4 vectorized) -------------------------------
__global__ void gating_kernel(const float* __restrict__ x,
                              const float* __restrict__ wg)
{
    __shared__ float ws[E_ * D_];
    for (int i = threadIdx.x; i < E_ * D_ / 4; i += blockDim.x)
        ((float4*)ws)[i] = ((const float4*)wg)[i];
    __syncthreads();

    const int warp = threadIdx.x >> 5, lane = threadIdx.x & 31;
    const int b = blockIdx.x * 8 + warp;
    const float4* xr = (const float4*)(x + (size_t)b * D_);

    float acc[E_];
#pragma unroll
    for (int e = 0; e < E_; e++) acc[e] = 0.f;
    for (int d4 = lane; d4 < D_ / 4; d4 += 32) {
        float4 xv = __ldg(&xr[d4]);
#pragma unroll
        for (int e = 0; e < E_; e++) {
            float4 wv = ((const float4*)(ws + e * D_))[d4];
            acc[e] = fmaf(xv.x, wv.x, acc[e]);
            acc[e] = fmaf(xv.y, wv.y, acc[e]);
            acc[e] = fmaf(xv.z, wv.z, acc[e]);
            acc[e] = fmaf(xv.w, wv.w, acc[e]);
        }
    }
#pragma unroll
    for (int e = 0; e < E_; e++) {
#pragma unroll
        for (int o = 16; o; o >>= 1) acc[e] += __shfl_down_sync(0xffffffffu, acc[e], o);
    }
    if (lane == 0) {
        int i0 = 0; float v0 = acc[0];
#pragma unroll
        for (int e = 1; e < E_; e++) if (acc[e] > v0) { v0 = acc[e]; i0 = e; }
        int i1 = -1; float v1 = -INFINITY;
#pragma unroll
        for (int e = 0; e < E_; e++) if (e != i0 && acc[e] > v1) { v1 = acc[e]; i1 = e; }
        float t  = expf(v1 - v0);
        float gA = 1.f / (1.f + t);
        float gB = t / (1.f + t);
        g_eidx[b * 2 + 0] = i0;  g_eidx[b * 2 + 1] = i1;
        g_gval[b * 2 + 0] = gA;  g_gval[b * 2 + 1] = gB;
    }
}

// ---------------- 2+3) merged per-expert stats + scan + loss -------------------
// Single block: 8 warps, warp e reduces expert e; thread 0 finishes scan+loss.
__global__ void stats_scan_kernel(float* __restrict__ out)
{
    __shared__ float simp[E_];
    __shared__ int   scnt[E_];

    const int warp = threadIdx.x >> 5;      // 0..7 = expert id
    const int lane = threadIdx.x & 31;

    float imp = 0.f; int cnt = 0;
    for (int i = lane; i < NSLOT; i += 32)
        if (g_eidx[i] == warp) { imp += g_gval[i]; cnt++; }
#pragma unroll
    for (int o = 16; o; o >>= 1) {
        imp += __shfl_down_sync(0xffffffffu, imp, o);
        cnt += __shfl_down_sync(0xffffffffu, cnt, o);
    }
    if (lane == 0) { simp[warp] = imp; scnt[warp] = cnt; }
    __syncthreads();

    if (threadIdx.x == 0) {
        int off = 0;
        for (int e = 0; e < E_; e++) {
            g_off[e] = off; g_cur[e] = off;
            g_cnt[e] = scnt[e];
            off += ((scnt[e] + 127) >> 7) << 7;
        }
        g_off[E_] = off;
        float mi = 0.f, ml = 0.f;
        for (int e = 0; e < E_; e++) { mi += simp[e]; ml += (float)scnt[e]; }
        mi *= (1.f / E_); ml *= (1.f / E_);
        float vi = 0.f, vl = 0.f;
        for (int e = 0; e < E_; e++) {
            float di = simp[e] - mi;         vi += di * di;
            float dl = (float)scnt[e] - ml;  vl += dl * dl;
        }
        vi *= (1.f / (E_ - 1)); vl *= (1.f / (E_ - 1));
        out[(size_t)B_ * D_] = (vi / (mi * mi + 1e-10f) + vl / (ml * ml + 1e-10f)) * 0.01f;
    }
}

// ---------------- 4) scatter ---------------------------------------------------
__global__ void scatter_kernel()
{
    int i = blockIdx.x * blockDim.x + threadIdx.x;
    if (i < NSLOT) {
        int e = g_eidx[i];
        int pos = atomicAdd(&g_cur[e], 1);
        g_tok[pos] = i >> 1;
        g_pos[i] = pos;
    }
}

// ---------------- 5/6) grouped GEMM, 128x128, 2-stage cp.async (R11 config) ---
#define LDS_ 72
#define MAT_HALVES (128 * LDS_)               // 9216 per matrix per stage
#define STG_BYTES  (2 * MAT_HALVES * 2)       // 36864
#define SMEM_TOT   (2 * STG_BYTES)            // 73728  (>= 128*272 staging)

template<int NFULL, int KDIM, bool PH1, bool NMAJOR>
__global__ __launch_bounds__(256, 2)
void gemm_mma(const __half* __restrict__ A, const __half* __restrict__ W,
              const float* __restrict__ bias)
{
    extern __shared__ __half smem[];

    const int row0 = (NMAJOR ? blockIdx.y : blockIdx.x) * 128;
    if (row0 >= g_off[E_]) return;

    int e = 0;
#pragma unroll
    for (int i = 0; i < E_; i++) if (row0 >= g_off[i + 1]) e = i + 1;
    const int rowEnd = g_off[e] + g_cnt[e];

    const int tid = threadIdx.x;
    const int w = tid >> 5, lane = tid & 31;
    const int wm = w & 3, wn = w >> 2;
    const int n0 = (NMAJOR ? blockIdx.x : blockIdx.y) * 128;
    const __half* We = W + (size_t)e * NFULL * KDIM;

    const uint32_t sb = smem_u32(smem);

    const __half* pB[4];
    const __half* pA[4];
    uint32_t offA[4], offB[4];
#pragma unroll
    for (int i = 0; i < 4; i++) {
        int idx = tid + i * 256;
        int row = idx >> 3, q = idx & 7;
        offA[i] = (row * LDS_ + q * 8) * 2;
        offB[i] = (MAT_HALVES + row * LDS_ + q * 8) * 2;
        pB[i] = We + (size_t)(n0 + row) * KDIM + q * 8;
        if (PH1) {
            int tok = g_tok[row0 + row];
            pA[i] = A + (size_t)tok * KDIM + q * 8;
        } else {
            pA[i] = A + (size_t)(row0 + row) * KDIM + q * 8;
        }
    }

    float acc[2][8][4];
#pragma unroll
    for (int a = 0; a < 2; a++)
#pragma unroll
        for (int b = 0; b < 8; b++)
#pragma unroll
            for (int c = 0; c < 4; c++) acc[a][b][c] = 0.f;

    const int NC = KDIM / 64;

    // prologue: stage 0
    {
#pragma unroll
        for (int i = 0; i < 4; i++) {
            cp16(sb + offA[i], pA[i]);
            cp16(sb + offB[i], pB[i]);
        }
        cp_commit();
    }

    for (int c = 0; c < NC; c++) {
        cp_wait0();
        __syncthreads();

        if (c + 1 < NC) {
            const int k1 = (c + 1) * 64;
            uint32_t base = sb + ((c + 1) & 1) * STG_BYTES;
#pragma unroll
            for (int i = 0; i < 4; i++) {
                cp16(base + offA[i], pA[i] + k1);
                cp16(base + offB[i], pB[i] + k1);
            }
            cp_commit();
        }

        const uint32_t sbA = sb + (c & 1) * STG_BYTES;
        const uint32_t sbB = sbA + MAT_HALVES * 2;

#pragma unroll
        for (int ks = 0; ks < 4; ks++) {
            const int kk = ks * 16;
            uint32_t aF[2][4];
            uint32_t aoff = ((wm * 32 + (lane & 15)) * LDS_ + kk + ((lane >> 4) << 3)) * 2;
#pragma unroll
            for (int mf = 0; mf < 2; mf++)
                ldmx4(aF[mf][0], aF[mf][1], aF[mf][2], aF[mf][3], sbA + aoff + mf * 16 * LDS_ * 2);

            uint32_t boff = ((wn * 64 + ((lane >> 4) << 3) + (lane & 7)) * LDS_
                             + kk + (((lane >> 3) & 1) << 3)) * 2;
#pragma unroll
            for (int j2 = 0; j2 < 4; j2++) {
                uint32_t bf[4];
                ldmx4(bf[0], bf[1], bf[2], bf[3], sbB + boff + j2 * 16 * LDS_ * 2);
#pragma unroll
                for (int mf = 0; mf < 2; mf++) {
#pragma unroll
                    for (int nf = 0; nf < 2; nf++)
                        mma16816(acc[mf][j2 * 2 + nf], aF[mf], bf[2 * nf], bf[2 * nf + 1]);
                }
            }
        }
    }
    cp_wait0();
    __syncthreads();   // all ldsm done; smem free for staging

    // ---- epilogue: stage tile in SMEM, then coalesced 16B stores ----
    const int g = lane >> 2, cpair = lane & 3;
#pragma unroll
    for (int mf = 0; mf < 2; mf++) {
#pragma unroll
        for (int nf = 0; nf < 8; nf++) {
            int col = wn * 64 + nf * 8 + 2 * cpair;
            float b0 = __ldg(&bias[(size_t)e * NFULL + n0 + col]);
            float b1 = __ldg(&bias[(size_t)e * NFULL + n0 + col + 1]);
            float* cc = acc[mf][nf];
#pragma unroll
            for (int half = 0; half < 2; half++) {
                int lrow = wm * 32 + mf * 16 + half * 8 + g;
                float v0 = cc[half * 2 + 0] + b0;
                float v1 = cc[half * 2 + 1] + b1;
                if (PH1) {
                    v0 = 0.5f * v0 * (1.0f + erff(v0 * 0.7071067811865476f));
                    v1 = 0.5f * v1 * (1.0f + erff(v1 * 0.7071067811865476f));
                }
                __half2 hw = __floats2half2_rn(v0, v1);
                *(uint32_t*)((char*)smem + (lrow * 136 + col) * 2) = *(uint32_t*)&hw;
            }
        }
    }
    __syncthreads();

    __half* dstBase = PH1 ? g_h : g_o;
    for (int i = tid; i < 128 * 16; i += 256) {
        int row = i >> 4, seg = i & 15;
        int r = row0 + row;
        if (r < rowEnd) {
            uint4 v = *(uint4*)((char*)smem + row * 272 + seg * 16);
            *(uint4*)&dstBase[(size_t)r * NFULL + n0 + seg * 8] = v;
        }
    }
}

// ---------------- 7) dual softmax + combine + log -----------------------------
__global__ void combine_kernel(float* __restrict__ out)
{
    __shared__ float s0[D_], s1[D_];
    __shared__ float r0[8], r1[8];

    const int b = blockIdx.x;
    const int tid = threadIdx.x;
    const int lane = tid & 31, warp = tid >> 5;

    const int   p0 = g_pos[b * 2 + 0], p1 = g_pos[b * 2 + 1];
    const float gg0 = g_gval[b * 2 + 0], gg1 = g_gval[b * 2 + 1];
    const __half2* q0 = (const __half2*)(g_o + (size_t)p0 * D_);
    const __half2* q1 = (const __half2*)(g_o + (size_t)p1 * D_);

    float m0 = -INFINITY, m1 = -INFINITY;
    for (int d2 = tid; d2 < D_ / 2; d2 += 256) {
        float2 v0 = __half22float2(q0[d2]);
        float2 v1 = __half22float2(q1[d2]);
        s0[2 * d2] = v0.x; s0[2 * d2 + 1] = v0.y;
        s1[2 * d2] = v1.x; s1[2 * d2 + 1] = v1.y;
        m0 = fmaxf(m0, fmaxf(v0.x, v0.y));
        m1 = fmaxf(m1, fmaxf(v1.x, v1.y));
    }
#pragma unroll
    for (int o = 16; o; o >>= 1) {
        m0 = fmaxf(m0, __shfl_down_sync(0xffffffffu, m0, o));
        m1 = fmaxf(m1, __shfl_down_sync(0xffffffffu, m1, o));
    }
    if (lane == 0) { r0[warp] = m0; r1[warp] = m1; }
    __syncthreads();
    if (tid == 0) {
        float a = r0[0], c = r1[0];
        for (int i = 1; i < 8; i++) { a = fmaxf(a, r0[i]); c = fmaxf(c, r1[i]); }
        r0[0] = a; r1[0] = c;
    }
    __syncthreads();
    m0 = r0[0]; m1 = r1[0];

    float e0 = 0.f, e1 = 0.f;
    for (int d = tid; d < D_; d += 256) {
        e0 += expf(s0[d] - m0);
        e1 += expf(s1[d] - m1);
    }
#pragma unroll
    for (int o = 16; o; o >>= 1) {
        e0 += __shfl_down_sync(0xffffffffu, e0, o);
        e1 += __shfl_down_sync(0xffffffffu, e1, o);
    }
    __syncthreads();
    if (lane == 0) { r0[warp] = e0; r1[warp] = e1; }
    __syncthreads();
    if (tid == 0) {
        float a = 0.f, c = 0.f;
        for (int i = 0; i < 8; i++) { a += r0[i]; c += r1[i]; }
        r0[0] = a; r1[0] = c;
    }
    __syncthreads();
    const float c0 = gg0 / r0[0];
    const float c1 = gg1 / r1[0];

    for (int d = tid; d < D_; d += 256) {
        float c = c0 * expf(s0[d] - m0) + c1 * expf(s1[d] - m1);
        if (c == 0.f) c = 2.2204460492503131e-16f;
        out[(size_t)b * D_ + d] = logf(c);
    }
}

// ---------------- launch --------------------------------------------------------
extern "C" void kernel_launch(void* const* d_in, const int* in_sizes, int n_in,
                              void* d_out, int out_size)
{
    const float* x    = (const float*)d_in[0];
    const float* wg   = (const float*)d_in[1];
    const float* fc1w = (const float*)d_in[2];
    const float* fc1b = (const float*)d_in[3];
    const float* fc2w = (const float*)d_in[4];
    const float* fc2b = (const float*)d_in[5];
    float* out = (float*)d_out;

    __half* xh;  cudaGetSymbolAddress((void**)&xh,  g_xh);
    __half* w1h; cudaGetSymbolAddress((void**)&w1h, g_w1h);
    __half* w2h; cudaGetSymbolAddress((void**)&w2h, g_w2h);
    __half* hh;  cudaGetSymbolAddress((void**)&hh,  g_h);

    static cudaStream_t s1 = nullptr, s2 = nullptr;
    static cudaEvent_t ev0 = nullptr, ev1 = nullptr, ev2 = nullptr;
    if (!s1) {
        cudaStreamCreateWithFlags(&s1, cudaStreamNonBlocking);
        cudaStreamCreateWithFlags(&s2, cudaStreamNonBlocking);
        cudaEventCreateWithFlags(&ev0, cudaEventDisableTiming);
        cudaEventCreateWithFlags(&ev1, cudaEventDisableTiming);
        cudaEventCreateWithFlags(&ev2, cudaEventDisableTiming);
        cudaFuncSetAttribute(gemm_mma<H_, D_, true, false>,
                             cudaFuncAttributeMaxDynamicSharedMemorySize, SMEM_TOT);
        cudaFuncSetAttribute(gemm_mma<D_, H_, false, true>,
                             cudaFuncAttributeMaxDynamicSharedMemorySize, SMEM_TOT);
    }

    const int nW = E_ * H_ * D_ / 8;     // 4194304
    const int nX = B_ * D_ / 8;          // 1048576

    cudaEventRecord(ev0, 0);
    cudaStreamWaitEvent(s1, ev0, 0);
    cudaStreamWaitEvent(s2, ev0, 0);

    cvt_f2h<<<(nX + 255) / 256, 256, 0, s1>>>((const float4*)x,    (uint4*)xh,  nX);
    cvt_f2h<<<(nW + 255) / 256, 256, 0, s1>>>((const float4*)fc1w, (uint4*)w1h, nW);
    cudaEventRecord(ev1, s1);

    cvt_f2h<<<(nW + 255) / 256, 256, 0, s2>>>((const float4*)fc2w, (uint4*)w2h, nW);
    cudaEventRecord(ev2, s2);

    gating_kernel<<<B_ / 8, 256>>>(x, wg);
    stats_scan_kernel<<<1, 256>>>(out);
    scatter_kernel<<<(NSLOT + 255) / 256, 256>>>();

    cudaStreamWaitEvent(0, ev1, 0);
    gemm_mma<H_, D_, true, false><<<dim3(RMAX / 128, H_ / 128), 256, SMEM_TOT>>>(xh, w1h, fc1b);

    cudaStreamWaitEvent(0, ev2, 0);
    gemm_mma<D_, H_, false, true><<<dim3(D_ / 128, RMAX / 128), 256, SMEM_TOT>>>(hh, w2h, fc2b);

    combine_kernel<<<B_, 256>>>(out);
}

// round 16
// speedup vs baseline: 1.0428x; 1.0427x over previous
#include <cuda_runtime.h>
#include <cuda_fp16.h>
#include <math.h>
#include <stdint.h>

#define B_    8192
#define D_    1024
#define H_    4096
#define E_    8
#define NSLOT (B_ * 2)
#define RMAX  17408   // 16384 + 8*128 tile padding

// ---------------- scratch (device globals: allocation-free) ----------------
__device__ __align__(128) __half g_h[(size_t)RMAX * H_];     // gelu(fc1), fp16
__device__ __align__(128) __half g_o[(size_t)RMAX * D_];     // fc2 out, fp16
__device__ __align__(128) __half g_xh[(size_t)B_ * D_];      // x in fp16
__device__ __align__(128) __half g_w1h[(size_t)E_ * H_ * D_];
__device__ __align__(128) __half g_w2h[(size_t)E_ * D_ * H_];
__device__ int   g_tok[RMAX];
__device__ int   g_pos[NSLOT];
__device__ int   g_eidx[NSLOT];
__device__ float g_gval[NSLOT];
__device__ int   g_cnt[E_];
__device__ int   g_cur[E_];
__device__ int   g_off[E_ + 1];
__device__ float g_imp[E_];

// ---------------- helpers ----------------------------------------------------
__device__ __forceinline__ uint32_t smem_u32(const void* p) {
    uint32_t a;
    asm("{ .reg .u64 t; cvta.to.shared.u64 t, %1; cvt.u32.u64 %0, t; }" : "=r"(a) : "l"(p));
    return a;
}
__device__ __forceinline__ void ldmx4(uint32_t& r0, uint32_t& r1, uint32_t& r2, uint32_t& r3,
                                      uint32_t addr) {
    asm volatile("ldmatrix.sync.aligned.m8n8.x4.shared.b16 {%0,%1,%2,%3}, [%4];"
                 : "=r"(r0), "=r"(r1), "=r"(r2), "=r"(r3) : "r"(addr));
}
__device__ __forceinline__ void mma16816(float* c, const uint32_t* a, uint32_t b0, uint32_t b1) {
    asm volatile("mma.sync.aligned.m16n8k16.row.col.f32.f16.f16.f32 "
                 "{%0,%1,%2,%3}, {%4,%5,%6,%7}, {%8,%9}, {%0,%1,%2,%3};"
                 : "+f"(c[0]), "+f"(c[1]), "+f"(c[2]), "+f"(c[3])
                 : "r"(a[0]), "r"(a[1]), "r"(a[2]), "r"(a[3]), "r"(b0), "r"(b1));
}
__device__ __forceinline__ void cp16(uint32_t dst, const void* src) {
    asm volatile("cp.async.cg.shared.global [%0], [%1], 16;" :: "r"(dst), "l"(src));
}
__device__ __forceinline__ void cp_commit() {
    asm volatile("cp.async.commit_group;" ::: "memory");
}
__device__ __forceinline__ void cp_wait0() {
    asm volatile("cp.async.wait_group 0;" ::: "memory");
}

// ---------------- 0) fp32 -> fp16 conversion ---------------------------------
__global__ void cvt_f2h(const float4* __restrict__ src, uint4* __restrict__ dst, int n8)
{
    int i = blockIdx.x * blockDim.x + threadIdx.x;
    if (i < n8) {
        float4 a = __ldg(&src[2 * i]);
        float4 b = __ldg(&src[2 * i + 1]);
        __half2 h0 = __floats2half2_rn(a.x, a.y);
        __half2 h1 = __floats2half2_rn(a.z, a.w);
        __half2 h2 = __floats2half2_rn(b.x, b.y);
        __half2 h3 = __floats2half2_rn(b.z, b.w);
        dst[i] = make_uint4(*(uint32_t*)&h0, *(uint32_t*)&h1,
                            *(uint32_t*)&h2, *(uint32_t*)&h3);
    }
}

// ---------------- 1) gating (float4 vectorized) -------------------------------
__global__ void gating_kernel(const float* __restrict__ x,
                              const float* __restrict__ wg)
{
    __shared__ float ws[E_ * D_];
    for (int i = threadIdx.x; i < E_ * D_ / 4; i += blockDim.x)
        ((float4*)ws)[i] = ((const float4*)wg)[i];
    __syncthreads();

    const int warp = threadIdx.x >> 5, lane = threadIdx.x & 31;
    const int b = blockIdx.x * 8 + warp;
    const float4* xr = (const float4*)(x + (size_t)b * D_);

    float acc[E_];
#pragma unroll
    for (int e = 0; e < E_; e++) acc[e] = 0.f;
    for (int d4 = lane; d4 < D_ / 4; d4 += 32) {
        float4 xv = __ldg(&xr[d4]);
#pragma unroll
        for (int e = 0; e < E_; e++) {
            float4 wv = ((const float4*)(ws + e * D_))[d4];
            acc[e] = fmaf(xv.x, wv.x, acc[e]);
            acc[e] = fmaf(xv.y, wv.y, acc[e]);
            acc[e] = fmaf(xv.z, wv.z, acc[e]);
            acc[e] = fmaf(xv.w, wv.w, acc[e]);
        }
    }
#pragma unroll
    for (int e = 0; e < E_; e++) {
#pragma unroll
        for (int o = 16; o; o >>= 1) acc[e] += __shfl_down_sync(0xffffffffu, acc[e], o);
    }
    if (lane == 0) {
        int i0 = 0; float v0 = acc[0];
#pragma unroll
        for (int e = 1; e < E_; e++) if (acc[e] > v0) { v0 = acc[e]; i0 = e; }
        int i1 = -1; float v1 = -INFINITY;
#pragma unroll
        for (int e = 0; e < E_; e++) if (e != i0 && acc[e] > v1) { v1 = acc[e]; i1 = e; }
        float t  = expf(v1 - v0);
        float gA = 1.f / (1.f + t);
        float gB = t / (1.f + t);
        g_eidx[b * 2 + 0] = i0;  g_eidx[b * 2 + 1] = i1;
        g_gval[b * 2 + 0] = gA;  g_gval[b * 2 + 1] = gB;
    }
}

// ---------------- 2) per-expert stats ----------------------------------------
__global__ void expert_stats_kernel()
{
    const int e = blockIdx.x;
    const int tid = threadIdx.x;
    float imp = 0.f; int cnt = 0;
    for (int i = tid; i < NSLOT; i += 256)
        if (g_eidx[i] == e) { imp += g_gval[i]; cnt++; }
    __shared__ float simp[256];
    __shared__ int   scnt[256];
    simp[tid] = imp; scnt[tid] = cnt;
    __syncthreads();
    for (int s = 128; s; s >>= 1) {
        if (tid < s) { simp[tid] += simp[tid + s]; scnt[tid] += scnt[tid + s]; }
        __syncthreads();
    }
    if (tid == 0) { g_imp[e] = simp[0]; g_cnt[e] = scnt[0]; }
}

// ---------------- 3) scan + loss ----------------------------------------------
__global__ void scan_loss_kernel(float* __restrict__ out)
{
    if (threadIdx.x == 0 && blockIdx.x == 0) {
        int off = 0;
        for (int e = 0; e < E_; e++) {
            g_off[e] = off; g_cur[e] = off;
            off += ((g_cnt[e] + 127) >> 7) << 7;
        }
        g_off[E_] = off;
        float mi = 0.f, ml = 0.f;
        for (int e = 0; e < E_; e++) { mi += g_imp[e]; ml += (float)g_cnt[e]; }
        mi *= (1.f / E_); ml *= (1.f / E_);
        float vi = 0.f, vl = 0.f;
        for (int e = 0; e < E_; e++) {
            float di = g_imp[e] - mi;        vi += di * di;
            float dl = (float)g_cnt[e] - ml; vl += dl * dl;
        }
        vi *= (1.f / (E_ - 1)); vl *= (1.f / (E_ - 1));
        out[(size_t)B_ * D_] = (vi / (mi * mi + 1e-10f) + vl / (ml * ml + 1e-10f)) * 0.01f;
    }
}

// ---------------- 4) scatter ---------------------------------------------------
__global__ void scatter_kernel()
{
    int i = blockIdx.x * blockDim.x + threadIdx.x;
    if (i < NSLOT) {
        int e = g_eidx[i];
        int pos = atomicAdd(&g_cur[e], 1);
        g_tok[pos] = i >> 1;
        g_pos[i] = pos;
    }
}

// ---------------- 5/6) grouped GEMM, 128x128, 2-stage cp.async ----------------
// NMAJOR=false: blockIdx.x = m-block (GEMM1). NMAJOR=true: x = n-block (GEMM2).
// SMEM padded row stride 72 halves (144B = 9x16B) -> ldmatrix conflict-free.
// Epilogue stages the output tile in SMEM then writes coalesced 16B stores.
#define LDS_ 72
#define MAT_HALVES (128 * LDS_)               // 9216 per matrix per stage
#define STG_BYTES  (2 * MAT_HALVES * 2)       // 36864
#define SMEM_TOT   (2 * STG_BYTES)            // 73728  (>= 128*272 staging)

template<int NFULL, int KDIM, bool PH1, bool NMAJOR>
__global__ __launch_bounds__(256, 2)
void gemm_mma(const __half* __restrict__ A, const __half* __restrict__ W,
              const float* __restrict__ bias)
{
    extern __shared__ __half smem[];

    const int row0 = (NMAJOR ? blockIdx.y : blockIdx.x) * 128;
    if (row0 >= g_off[E_]) return;

    int e = 0;
#pragma unroll
    for (int i = 0; i < E_; i++) if (row0 >= g_off[i + 1]) e = i + 1;
    const int rowEnd = g_off[e] + g_cnt[e];

    const int tid = threadIdx.x;
    const int w = tid >> 5, lane = tid & 31;
    const int wm = w & 3, wn = w >> 2;
    const int n0 = (NMAJOR ? blockIdx.x : blockIdx.y) * 128;
    const __half* We = W + (size_t)e * NFULL * KDIM;

    const uint32_t sb = smem_u32(smem);

    const __half* pB[4];
    const __half* pA[4];
    uint32_t offA[4], offB[4];
#pragma unroll
    for (int i = 0; i < 4; i++) {
        int idx = tid + i * 256;
        int row = idx >> 3, q = idx & 7;
        offA[i] = (row * LDS_ + q * 8) * 2;
        offB[i] = (MAT_HALVES + row * LDS_ + q * 8) * 2;
        pB[i] = We + (size_t)(n0 + row) * KDIM + q * 8;
        if (PH1) {
            int tok = g_tok[row0 + row];
            pA[i] = A + (size_t)tok * KDIM + q * 8;
        } else {
            pA[i] = A + (size_t)(row0 + row) * KDIM + q * 8;
        }
    }

    float acc[2][8][4];
#pragma unroll
    for (int a = 0; a < 2; a++)
#pragma unroll
        for (int b = 0; b < 8; b++)
#pragma unroll
            for (int c = 0; c < 4; c++) acc[a][b][c] = 0.f;

    const int NC = KDIM / 64;

    // prologue: stage 0
    {
#pragma unroll
        for (int i = 0; i < 4; i++) {
            cp16(sb + offA[i], pA[i]);
            cp16(sb + offB[i], pB[i]);
        }
        cp_commit();
    }

    for (int c = 0; c < NC; c++) {
        cp_wait0();
        __syncthreads();

        if (c + 1 < NC) {
            const int k1 = (c + 1) * 64;
            uint32_t base = sb + ((c + 1) & 1) * STG_BYTES;
#pragma unroll
            for (int i = 0; i < 4; i++) {
                cp16(base + offA[i], pA[i] + k1);
                cp16(base + offB[i], pB[i] + k1);
            }
            cp_commit();
        }

        const uint32_t sbA = sb + (c & 1) * STG_BYTES;
        const uint32_t sbB = sbA + MAT_HALVES * 2;

#pragma unroll
        for (int ks = 0; ks < 4; ks++) {
            const int kk = ks * 16;
            uint32_t aF[2][4];
            uint32_t aoff = ((wm * 32 + (lane & 15)) * LDS_ + kk + ((lane >> 4) << 3)) * 2;
#pragma unroll
            for (int mf = 0; mf < 2; mf++)
                ldmx4(aF[mf][0], aF[mf][1], aF[mf][2], aF[mf][3], sbA + aoff + mf * 16 * LDS_ * 2);

            uint32_t boff = ((wn * 64 + ((lane >> 4) << 3) + (lane & 7)) * LDS_
                             + kk + (((lane >> 3) & 1) << 3)) * 2;
#pragma unroll
            for (int j2 = 0; j2 < 4; j2++) {
                uint32_t bf[4];
                ldmx4(bf[0], bf[1], bf[2], bf[3], sbB + boff + j2 * 16 * LDS_ * 2);
#pragma unroll
                for (int mf = 0; mf < 2; mf++) {
#pragma unroll
                    for (int nf = 0; nf < 2; nf++)
                        mma16816(acc[mf][j2 * 2 + nf], aF[mf], bf[2 * nf], bf[2 * nf + 1]);
                }
            }
        }
    }
    cp_wait0();
    __syncthreads();   // all ldsm done; smem free for staging

    // ---- epilogue: stage tile in SMEM, then coalesced 16B stores ----
    const int g = lane >> 2, cpair = lane & 3;
#pragma unroll
    for (int mf = 0; mf < 2; mf++) {
#pragma unroll
        for (int nf = 0; nf < 8; nf++) {
            int col = wn * 64 + nf * 8 + 2 * cpair;
            float b0 = __ldg(&bias[(size_t)e * NFULL + n0 + col]);
            float b1 = __ldg(&bias[(size_t)e * NFULL + n0 + col + 1]);
            float* cc = acc[mf][nf];
#pragma unroll
            for (int half = 0; half < 2; half++) {
                int lrow = wm * 32 + mf * 16 + half * 8 + g;
                float v0 = cc[half * 2 + 0] + b0;
                float v1 = cc[half * 2 + 1] + b1;
                if (PH1) {
                    v0 = 0.5f * v0 * (1.0f + erff(v0 * 0.7071067811865476f));
                    v1 = 0.5f * v1 * (1.0f + erff(v1 * 0.7071067811865476f));
                }
                __half2 hw = __floats2half2_rn(v0, v1);
                *(uint32_t*)((char*)smem + (lrow * 136 + col) * 2) = *(uint32_t*)&hw;
            }
        }
    }
    __syncthreads();

    __half* dstBase = PH1 ? g_h : g_o;
    for (int i = tid; i < 128 * 16; i += 256) {
        int row = i >> 4, seg = i & 15;
        int r = row0 + row;
        if (r < rowEnd) {
            uint4 v = *(uint4*)((char*)smem + row * 272 + seg * 16);
            *(uint4*)&dstBase[(size_t)r * NFULL + n0 + seg * 8] = v;
        }
    }
}

// ---------------- 7) dual softmax + combine + log -----------------------------
__global__ void combine_kernel(float* __restrict__ out)
{
    __shared__ float s0[D_], s1[D_];
    __shared__ float r0[8], r1[8];

    const int b = blockIdx.x;
    const int tid = threadIdx.x;
    const int lane = tid & 31, warp = tid >> 5;

    const int   p0 = g_pos[b * 2 + 0], p1 = g_pos[b * 2 + 1];
    const float gg0 = g_gval[b * 2 + 0], gg1 = g_gval[b * 2 + 1];
    const __half* q0 = g_o + (size_t)p0 * D_;
    const __half* q1 = g_o + (size_t)p1 * D_;

    float m0 = -INFINITY, m1 = -INFINITY;
    for (int d = tid; d < D_; d += 256) {
        float v0 = __half2float(q0[d]), v1 = __half2float(q1[d]);
        s0[d] = v0; s1[d] = v1;
        m0 = fmaxf(m0, v0); m1 = fmaxf(m1, v1);
    }
#pragma unroll
    for (int o = 16; o; o >>= 1) {
        m0 = fmaxf(m0, __shfl_down_sync(0xffffffffu, m0, o));
        m1 = fmaxf(m1, __shfl_down_sync(0xffffffffu, m1, o));
    }
    if (lane == 0) { r0[warp] = m0; r1[warp] = m1; }
    __syncthreads();
    if (tid == 0) {
        float a = r0[0], c = r1[0];
        for (int i = 1; i < 8; i++) { a = fmaxf(a, r0[i]); c = fmaxf(c, r1[i]); }
        r0[0] = a; r1[0] = c;
    }
    __syncthreads();
    m0 = r0[0]; m1 = r1[0];

    float e0 = 0.f, e1 = 0.f;
    for (int d = tid; d < D_; d += 256) {
        e0 += expf(s0[d] - m0);
        e1 += expf(s1[d] - m1);
    }
#pragma unroll
    for (int o = 16; o; o >>= 1) {
        e0 += __shfl_down_sync(0xffffffffu, e0, o);
        e1 += __shfl_down_sync(0xffffffffu, e1, o);
    }
    __syncthreads();
    if (lane == 0) { r0[warp] = e0; r1[warp] = e1; }
    __syncthreads();
    if (tid == 0) {
        float a = 0.f, c = 0.f;
        for (int i = 0; i < 8; i++) { a += r0[i]; c += r1[i]; }
        r0[0] = a; r1[0] = c;
    }
    __syncthreads();
    const float c0 = gg0 / r0[0];
    const float c1 = gg1 / r1[0];

    for (int d = tid; d < D_; d += 256) {
        float c = c0 * expf(s0[d] - m0) + c1 * expf(s1[d] - m1);
        if (c == 0.f) c = 2.2204460492503131e-16f;
        out[(size_t)b * D_ + d] = logf(c);
    }
}

// ---------------- launch --------------------------------------------------------
extern "C" void kernel_launch(void* const* d_in, const int* in_sizes, int n_in,
                              void* d_out, int out_size)
{
    const float* x    = (const float*)d_in[0];
    const float* wg   = (const float*)d_in[1];
    const float* fc1w = (const float*)d_in[2];
    const float* fc1b = (const float*)d_in[3];
    const float* fc2w = (const float*)d_in[4];
    const float* fc2b = (const float*)d_in[5];
    float* out = (float*)d_out;

    __half* xh;  cudaGetSymbolAddress((void**)&xh,  g_xh);
    __half* w1h; cudaGetSymbolAddress((void**)&w1h, g_w1h);
    __half* w2h; cudaGetSymbolAddress((void**)&w2h, g_w2h);
    __half* hh;  cudaGetSymbolAddress((void**)&hh,  g_h);

    static cudaStream_t s1 = nullptr, s2 = nullptr;
    static cudaEvent_t ev0 = nullptr, ev1 = nullptr, ev2 = nullptr;
    if (!s1) {
        cudaStreamCreateWithFlags(&s1, cudaStreamNonBlocking);
        cudaStreamCreateWithFlags(&s2, cudaStreamNonBlocking);
        cudaEventCreateWithFlags(&ev0, cudaEventDisableTiming);
        cudaEventCreateWithFlags(&ev1, cudaEventDisableTiming);
        cudaEventCreateWithFlags(&ev2, cudaEventDisableTiming);
        cudaFuncSetAttribute(gemm_mma<H_, D_, true, false>,
                             cudaFuncAttributeMaxDynamicSharedMemorySize, SMEM_TOT);
        cudaFuncSetAttribute(gemm_mma<D_, H_, false, true>,
                             cudaFuncAttributeMaxDynamicSharedMemorySize, SMEM_TOT);
    }

    const int nW = E_ * H_ * D_ / 8;     // 4194304
    const int nX = B_ * D_ / 8;          // 1048576

    cudaEventRecord(ev0, 0);
    cudaStreamWaitEvent(s1, ev0, 0);
    cudaStreamWaitEvent(s2, ev0, 0);

    cvt_f2h<<<(nX + 255) / 256, 256, 0, s1>>>((const float4*)x,    (uint4*)xh,  nX);
    cvt_f2h<<<(nW + 255) / 256, 256, 0, s1>>>((const float4*)fc1w, (uint4*)w1h, nW);
    cudaEventRecord(ev1, s1);

    cvt_f2h<<<(nW + 255) / 256, 256, 0, s2>>>((const float4*)fc2w, (uint4*)w2h, nW);
    cudaEventRecord(ev2, s2);

    gating_kernel<<<B_ / 8, 256>>>(x, wg);
    expert_stats_kernel<<<E_, 256>>>();
    scan_loss_kernel<<<1, 32>>>(out);
    scatter_kernel<<<(NSLOT + 255) / 256, 256>>>();

    cudaStreamWaitEvent(0, ev1, 0);
    gemm_mma<H_, D_, true, false><<<dim3(RMAX / 128, H_ / 128), 256, SMEM_TOT>>>(xh, w1h, fc1b);

    cudaStreamWaitEvent(0, ev2, 0);
    gemm_mma<D_, H_, false, true><<<dim3(D_ / 128, RMAX / 128), 256, SMEM_TOT>>>(hh, w2h, fc2b);

    combine_kernel<<<B_, 256>>>(out);
}

// round 17
// speedup vs baseline: 1.0592x; 1.0158x over previous
#include <cuda_runtime.h>
#include <cuda_fp16.h>
#include <math.h>
#include <stdint.h>

#define B_    8192
#define D_    1024
#define H_    4096
#define E_    8
#define NSLOT (B_ * 2)
#define RMAX  17408   // 16384 + 8*128 tile padding

// ---------------- scratch (device globals: allocation-free) ----------------
__device__ __align__(128) __half g_h[(size_t)RMAX * H_];     // gelu(fc1), fp16
__device__ __align__(128) __half g_o[(size_t)RMAX * D_];     // fc2 out, fp16
__device__ __align__(128) __half g_xh[(size_t)B_ * D_];      // x in fp16
__device__ __align__(128) __half g_w1h[(size_t)E_ * H_ * D_];
__device__ __align__(128) __half g_w2h[(size_t)E_ * D_ * H_];
__device__ int   g_tok[RMAX];
__device__ int   g_pos[NSLOT];
__device__ int   g_eidx[NSLOT];
__device__ float g_gval[NSLOT];
__device__ int   g_cnt[E_];
__device__ int   g_cur[E_];
__device__ int   g_off[E_ + 1];
__device__ float g_imp[E_];

// ---------------- helpers ----------------------------------------------------
__device__ __forceinline__ uint32_t smem_u32(const void* p) {
    uint32_t a;
    asm("{ .reg .u64 t; cvta.to.shared.u64 t, %1; cvt.u32.u64 %0, t; }" : "=r"(a) : "l"(p));
    return a;
}
__device__ __forceinline__ void ldmx4(uint32_t& r0, uint32_t& r1, uint32_t& r2, uint32_t& r3,
                                      uint32_t addr) {
    asm volatile("ldmatrix.sync.aligned.m8n8.x4.shared.b16 {%0,%1,%2,%3}, [%4];"
                 : "=r"(r0), "=r"(r1), "=r"(r2), "=r"(r3) : "r"(addr));
}
__device__ __forceinline__ void mma16816(float* c, const uint32_t* a, uint32_t b0, uint32_t b1) {
    asm volatile("mma.sync.aligned.m16n8k16.row.col.f32.f16.f16.f32 "
                 "{%0,%1,%2,%3}, {%4,%5,%6,%7}, {%8,%9}, {%0,%1,%2,%3};"
                 : "+f"(c[0]), "+f"(c[1]), "+f"(c[2]), "+f"(c[3])
                 : "r"(a[0]), "r"(a[1]), "r"(a[2]), "r"(a[3]), "r"(b0), "r"(b1));
}
__device__ __forceinline__ void cp16(uint32_t dst, const void* src) {
    asm volatile("cp.async.cg.shared.global [%0], [%1], 16;" :: "r"(dst), "l"(src));
}
__device__ __forceinline__ void cp_commit() {
    asm volatile("cp.async.commit_group;" ::: "memory");
}
__device__ __forceinline__ void cp_wait0() {
    asm volatile("cp.async.wait_group 0;" ::: "memory");
}

// ---------------- 0) fp32 -> fp16 conversion ---------------------------------
__global__ void cvt_f2h(const float4* __restrict__ src, uint4* __restrict__ dst, int n8)
{
    int i = blockIdx.x * blockDim.x + threadIdx.x;
    if (i < n8) {
        float4 a = __ldg(&src[2 * i]);
        float4 b = __ldg(&src[2 * i + 1]);
        __half2 h0 = __floats2half2_rn(a.x, a.y);
        __half2 h1 = __floats2half2_rn(a.z, a.w);
        __half2 h2 = __floats2half2_rn(b.x, b.y);
        __half2 h3 = __floats2half2_rn(b.z, b.w);
        dst[i] = make_uint4(*(uint32_t*)&h0, *(uint32_t*)&h1,
                            *(uint32_t*)&h2, *(uint32_t*)&h3);
    }
}

// ---------------- 1) gating (float4 vectorized) + fused x->fp16 ---------------
__global__ void gating_kernel(const float* __restrict__ x,
                              const float* __restrict__ wg,
                              __half* __restrict__ xh)
{
    __shared__ float ws[E_ * D_];
    for (int i = threadIdx.x; i < E_ * D_ / 4; i += blockDim.x)
        ((float4*)ws)[i] = ((const float4*)wg)[i];
    __syncthreads();

    const int warp = threadIdx.x >> 5, lane = threadIdx.x & 31;
    const int b = blockIdx.x * 8 + warp;
    const float4* xr = (const float4*)(x + (size_t)b * D_);
    uint2* xhr = (uint2*)(xh + (size_t)b * D_);

    float acc[E_];
#pragma unroll
    for (int e = 0; e < E_; e++) acc[e] = 0.f;
    for (int d4 = lane; d4 < D_ / 4; d4 += 32) {
        float4 xv = __ldg(&xr[d4]);
        // fused fp16 emit (same rounding as cvt_f2h)
        __half2 p0 = __floats2half2_rn(xv.x, xv.y);
        __half2 p1 = __floats2half2_rn(xv.z, xv.w);
        xhr[d4] = make_uint2(*(uint32_t*)&p0, *(uint32_t*)&p1);
#pragma unroll
        for (int e = 0; e < E_; e++) {
            float4 wv = ((const float4*)(ws + e * D_))[d4];
            acc[e] = fmaf(xv.x, wv.x, acc[e]);
            acc[e] = fmaf(xv.y, wv.y, acc[e]);
            acc[e] = fmaf(xv.z, wv.z, acc[e]);
            acc[e] = fmaf(xv.w, wv.w, acc[e]);
        }
    }
#pragma unroll
    for (int e = 0; e < E_; e++) {
#pragma unroll
        for (int o = 16; o; o >>= 1) acc[e] += __shfl_down_sync(0xffffffffu, acc[e], o);
    }
    if (lane == 0) {
        int i0 = 0; float v0 = acc[0];
#pragma unroll
        for (int e = 1; e < E_; e++) if (acc[e] > v0) { v0 = acc[e]; i0 = e; }
        int i1 = -1; float v1 = -INFINITY;
#pragma unroll
        for (int e = 0; e < E_; e++) if (e != i0 && acc[e] > v1) { v1 = acc[e]; i1 = e; }
        float t  = expf(v1 - v0);
        float gA = 1.f / (1.f + t);
        float gB = t / (1.f + t);
        g_eidx[b * 2 + 0] = i0;  g_eidx[b * 2 + 1] = i1;
        g_gval[b * 2 + 0] = gA;  g_gval[b * 2 + 1] = gB;
    }
}

// ---------------- 2) per-expert stats ----------------------------------------
__global__ void expert_stats_kernel()
{
    const int e = blockIdx.x;
    const int tid = threadIdx.x;
    float imp = 0.f; int cnt = 0;
    for (int i = tid; i < NSLOT; i += 256)
        if (g_eidx[i] == e) { imp += g_gval[i]; cnt++; }
    __shared__ float simp[256];
    __shared__ int   scnt[256];
    simp[tid] = imp; scnt[tid] = cnt;
    __syncthreads();
    for (int s = 128; s; s >>= 1) {
        if (tid < s) { simp[tid] += simp[tid + s]; scnt[tid] += scnt[tid + s]; }
        __syncthreads();
    }
    if (tid == 0) { g_imp[e] = simp[0]; g_cnt[e] = scnt[0]; }
}

// ---------------- 3) scan + loss ----------------------------------------------
__global__ void scan_loss_kernel(float* __restrict__ out)
{
    if (threadIdx.x == 0 && blockIdx.x == 0) {
        int off = 0;
        for (int e = 0; e < E_; e++) {
            g_off[e] = off; g_cur[e] = off;
            off += ((g_cnt[e] + 127) >> 7) << 7;
        }
        g_off[E_] = off;
        float mi = 0.f, ml = 0.f;
        for (int e = 0; e < E_; e++) { mi += g_imp[e]; ml += (float)g_cnt[e]; }
        mi *= (1.f / E_); ml *= (1.f / E_);
        float vi = 0.f, vl = 0.f;
        for (int e = 0; e < E_; e++) {
            float di = g_imp[e] - mi;        vi += di * di;
            float dl = (float)g_cnt[e] - ml; vl += dl * dl;
        }
        vi *= (1.f / (E_ - 1)); vl *= (1.f / (E_ - 1));
        out[(size_t)B_ * D_] = (vi / (mi * mi + 1e-10f) + vl / (ml * ml + 1e-10f)) * 0.01f;
    }
}

// ---------------- 4) scatter ---------------------------------------------------
__global__ void scatter_kernel()
{
    int i = blockIdx.x * blockDim.x + threadIdx.x;
    if (i < NSLOT) {
        int e = g_eidx[i];
        int pos = atomicAdd(&g_cur[e], 1);
        g_tok[pos] = i >> 1;
        g_pos[i] = pos;
    }
}

// ---------------- 5/6) grouped GEMM, 128x128, 2-stage cp.async ----------------
#define LDS_ 72
#define MAT_HALVES (128 * LDS_)               // 9216 per matrix per stage
#define STG_BYTES  (2 * MAT_HALVES * 2)       // 36864
#define SMEM_TOT   (2 * STG_BYTES)            // 73728  (>= 128*272 staging)

template<int NFULL, int KDIM, bool PH1, bool NMAJOR>
__global__ __launch_bounds__(256, 2)
void gemm_mma(const __half* __restrict__ A, const __half* __restrict__ W,
              const float* __restrict__ bias)
{
    extern __shared__ __half smem[];

    const int row0 = (NMAJOR ? blockIdx.y : blockIdx.x) * 128;
    if (row0 >= g_off[E_]) return;

    int e = 0;
#pragma unroll
    for (int i = 0; i < E_; i++) if (row0 >= g_off[i + 1]) e = i + 1;
    const int rowEnd = g_off[e] + g_cnt[e];

    const int tid = threadIdx.x;
    const int w = tid >> 5, lane = tid & 31;
    const int wm = w & 3, wn = w >> 2;
    const int n0 = (NMAJOR ? blockIdx.x : blockIdx.y) * 128;
    const __half* We = W + (size_t)e * NFULL * KDIM;

    const uint32_t sb = smem_u32(smem);

    const __half* pB[4];
    const __half* pA[4];
    uint32_t offA[4], offB[4];
#pragma unroll
    for (int i = 0; i < 4; i++) {
        int idx = tid + i * 256;
        int row = idx >> 3, q = idx & 7;
        offA[i] = (row * LDS_ + q * 8) * 2;
        offB[i] = (MAT_HALVES + row * LDS_ + q * 8) * 2;
        pB[i] = We + (size_t)(n0 + row) * KDIM + q * 8;
        if (PH1) {
            int tok = g_tok[row0 + row];
            pA[i] = A + (size_t)tok * KDIM + q * 8;
        } else {
            pA[i] = A + (size_t)(row0 + row) * KDIM + q * 8;
        }
    }

    float acc[2][8][4];
#pragma unroll
    for (int a = 0; a < 2; a++)
#pragma unroll
        for (int b = 0; b < 8; b++)
#pragma unroll
            for (int c = 0; c < 4; c++) acc[a][b][c] = 0.f;

    const int NC = KDIM / 64;

    // prologue: stage 0
    {
#pragma unroll
        for (int i = 0; i < 4; i++) {
            cp16(sb + offA[i], pA[i]);
            cp16(sb + offB[i], pB[i]);
        }
        cp_commit();
    }

    for (int c = 0; c < NC; c++) {
        cp_wait0();
        __syncthreads();

        if (c + 1 < NC) {
            const int k1 = (c + 1) * 64;
            uint32_t base = sb + ((c + 1) & 1) * STG_BYTES;
#pragma unroll
            for (int i = 0; i < 4; i++) {
                cp16(base + offA[i], pA[i] + k1);
                cp16(base + offB[i], pB[i] + k1);
            }
            cp_commit();
        }

        const uint32_t sbA = sb + (c & 1) * STG_BYTES;
        const uint32_t sbB = sbA + MAT_HALVES * 2;

#pragma unroll
        for (int ks = 0; ks < 4; ks++) {
            const int kk = ks * 16;
            uint32_t aF[2][4];
            uint32_t aoff = ((wm * 32 + (lane & 15)) * LDS_ + kk + ((lane >> 4) << 3)) * 2;
#pragma unroll
            for (int mf = 0; mf < 2; mf++)
                ldmx4(aF[mf][0], aF[mf][1], aF[mf][2], aF[mf][3], sbA + aoff + mf * 16 * LDS_ * 2);

            uint32_t boff = ((wn * 64 + ((lane >> 4) << 3) + (lane & 7)) * LDS_
                             + kk + (((lane >> 3) & 1) << 3)) * 2;
#pragma unroll
            for (int j2 = 0; j2 < 4; j2++) {
                uint32_t bf[4];
                ldmx4(bf[0], bf[1], bf[2], bf[3], sbB + boff + j2 * 16 * LDS_ * 2);
#pragma unroll
                for (int mf = 0; mf < 2; mf++) {
#pragma unroll
                    for (int nf = 0; nf < 2; nf++)
                        mma16816(acc[mf][j2 * 2 + nf], aF[mf], bf[2 * nf], bf[2 * nf + 1]);
                }
            }
        }
    }
    cp_wait0();
    __syncthreads();   // all ldsm done; smem free for staging

    // ---- epilogue: stage tile in SMEM, then coalesced 16B stores ----
    const int g = lane >> 2, cpair = lane & 3;
#pragma unroll
    for (int mf = 0; mf < 2; mf++) {
#pragma unroll
        for (int nf = 0; nf < 8; nf++) {
            int col = wn * 64 + nf * 8 + 2 * cpair;
            float b0 = __ldg(&bias[(size_t)e * NFULL + n0 + col]);
            float b1 = __ldg(&bias[(size_t)e * NFULL + n0 + col + 1]);
            float* cc = acc[mf][nf];
#pragma unroll
            for (int half = 0; half < 2; half++) {
                int lrow = wm * 32 + mf * 16 + half * 8 + g;
                float v0 = cc[half * 2 + 0] + b0;
                float v1 = cc[half * 2 + 1] + b1;
                if (PH1) {
                    v0 = 0.5f * v0 * (1.0f + erff(v0 * 0.7071067811865476f));
                    v1 = 0.5f * v1 * (1.0f + erff(v1 * 0.7071067811865476f));
                }
                __half2 hw = __floats2half2_rn(v0, v1);
                *(uint32_t*)((char*)smem + (lrow * 136 + col) * 2) = *(uint32_t*)&hw;
            }
        }
    }
    __syncthreads();

    __half* dstBase = PH1 ? g_h : g_o;
    for (int i = tid; i < 128 * 16; i += 256) {
        int row = i >> 4, seg = i & 15;
        int r = row0 + row;
        if (r < rowEnd) {
            uint4 v = *(uint4*)((char*)smem + row * 272 + seg * 16);
            *(uint4*)&dstBase[(size_t)r * NFULL + n0 + seg * 8] = v;
        }
    }
}

// ---------------- 7) dual softmax + combine + log -----------------------------
__global__ void combine_kernel(float* __restrict__ out)
{
    __shared__ float s0[D_], s1[D_];
    __shared__ float r0[8], r1[8];

    const int b = blockIdx.x;
    const int tid = threadIdx.x;
    const int lane = tid & 31, warp = tid >> 5;

    const int   p0 = g_pos[b * 2 + 0], p1 = g_pos[b * 2 + 1];
    const float gg0 = g_gval[b * 2 + 0], gg1 = g_gval[b * 2 + 1];
    const __half* q0 = g_o + (size_t)p0 * D_;
    const __half* q1 = g_o + (size_t)p1 * D_;

    float m0 = -INFINITY, m1 = -INFINITY;
    for (int d = tid; d < D_; d += 256) {
        float v0 = __half2float(q0[d]), v1 = __half2float(q1[d]);
        s0[d] = v0; s1[d] = v1;
        m0 = fmaxf(m0, v0); m1 = fmaxf(m1, v1);
    }
#pragma unroll
    for (int o = 16; o; o >>= 1) {
        m0 = fmaxf(m0, __shfl_down_sync(0xffffffffu, m0, o));
        m1 = fmaxf(m1, __shfl_down_sync(0xffffffffu, m1, o));
    }
    if (lane == 0) { r0[warp] = m0; r1[warp] = m1; }
    __syncthreads();
    if (tid == 0) {
        float a = r0[0], c = r1[0];
        for (int i = 1; i < 8; i++) { a = fmaxf(a, r0[i]); c = fmaxf(c, r1[i]); }
        r0[0] = a; r1[0] = c;
    }
    __syncthreads();
    m0 = r0[0]; m1 = r1[0];

    float e0 = 0.f, e1 = 0.f;
    for (int d = tid; d < D_; d += 256) {
        e0 += expf(s0[d] - m0);
        e1 += expf(s1[d] - m1);
    }
#pragma unroll
    for (int o = 16; o; o >>= 1) {
        e0 += __shfl_down_sync(0xffffffffu, e0, o);
        e1 += __shfl_down_sync(0xffffffffu, e1, o);
    }
    __syncthreads();
    if (lane == 0) { r0[warp] = e0; r1[warp] = e1; }
    __syncthreads();
    if (tid == 0) {
        float a = 0.f, c = 0.f;
        for (int i = 0; i < 8; i++) { a += r0[i]; c += r1[i]; }
        r0[0] = a; r1[0] = c;
    }
    __syncthreads();
    const float c0 = gg0 / r0[0];
    const float c1 = gg1 / r1[0];

    for (int d = tid; d < D_; d += 256) {
        float c = c0 * expf(s0[d] - m0) + c1 * expf(s1[d] - m1);
        if (c == 0.f) c = 2.2204460492503131e-16f;
        out[(size_t)b * D_ + d] = logf(c);
    }
}

// ---------------- launch --------------------------------------------------------
extern "C" void kernel_launch(void* const* d_in, const int* in_sizes, int n_in,
                              void* d_out, int out_size)
{
    const float* x    = (const float*)d_in[0];
    const float* wg   = (const float*)d_in[1];
    const float* fc1w = (const float*)d_in[2];
    const float* fc1b = (const float*)d_in[3];
    const float* fc2w = (const float*)d_in[4];
    const float* fc2b = (const float*)d_in[5];
    float* out = (float*)d_out;

    __half* xh;  cudaGetSymbolAddress((void**)&xh,  g_xh);
    __half* w1h; cudaGetSymbolAddress((void**)&w1h, g_w1h);
    __half* w2h; cudaGetSymbolAddress((void**)&w2h, g_w2h);
    __half* hh;  cudaGetSymbolAddress((void**)&hh,  g_h);

    static cudaStream_t s1 = nullptr, s2 = nullptr;
    static cudaEvent_t ev0 = nullptr, ev1 = nullptr, ev2 = nullptr;
    if (!s1) {
        cudaStreamCreateWithFlags(&s1, cudaStreamNonBlocking);
        cudaStreamCreateWithFlags(&s2, cudaStreamNonBlocking);
        cudaEventCreateWithFlags(&ev0, cudaEventDisableTiming);
        cudaEventCreateWithFlags(&ev1, cudaEventDisableTiming);
        cudaEventCreateWithFlags(&ev2, cudaEventDisableTiming);
        cudaFuncSetAttribute(gemm_mma<H_, D_, true, false>,
                             cudaFuncAttributeMaxDynamicSharedMemorySize, SMEM_TOT);
        cudaFuncSetAttribute(gemm_mma<D_, H_, false, true>,
                             cudaFuncAttributeMaxDynamicSharedMemorySize, SMEM_TOT);
    }

    const int nW = E_ * H_ * D_ / 8;     // 4194304

    cudaEventRecord(ev0, 0);
    cudaStreamWaitEvent(s1, ev0, 0);
    cudaStreamWaitEvent(s2, ev0, 0);

    // s1: fc1 weight conversion only (x conversion fused into gating)
    cvt_f2h<<<(nW + 255) / 256, 256, 0, s1>>>((const float4*)fc1w, (uint4*)w1h, nW);
    cudaEventRecord(ev1, s1);

    // s2: fc2 weight conversion (overlaps gating chain + GEMM1)
    cvt_f2h<<<(nW + 255) / 256, 256, 0, s2>>>((const float4*)fc2w, (uint4*)w2h, nW);
    cudaEventRecord(ev2, s2);

    gating_kernel<<<B_ / 8, 256>>>(x, wg, xh);
    expert_stats_kernel<<<E_, 256>>>();
    scan_loss_kernel<<<1, 32>>>(out);
    scatter_kernel<<<(NSLOT + 255) / 256, 256>>>();

    cudaStreamWaitEvent(0, ev1, 0);
    gemm_mma<H_, D_, true, false><<<dim3(RMAX / 128, H_ / 128), 256, SMEM_TOT>>>(xh, w1h, fc1b);

    cudaStreamWaitEvent(0, ev2, 0);
    gemm_mma<D_, H_, false, true><<<dim3(D_ / 128, RMAX / 128), 256, SMEM_TOT>>>(hh, w2h, fc2b);

    combine_kernel<<<B_, 256>>>(out);
}